// round 1
// baseline (speedup 1.0000x reference)
#include <cuda_runtime.h>

// out = sum(x) * a * b ; x is 8192*8192 fp32 (64Mi elements), a,b device scalars.
// Two-pass deterministic reduction: pass1 writes per-block partials to a
// __device__ global (allocation-free scratch), pass2 reduces + scales.

#define R1_BLOCKS 1184   // 8 CTAs per SM * 148 SMs
#define R1_THREADS 256

__device__ float g_partials[R1_BLOCKS];

__global__ __launch_bounds__(R1_THREADS) void reduce_pass1(
    const float4* __restrict__ x4, int n4)
{
    float s = 0.0f;
    int idx = blockIdx.x * R1_THREADS + threadIdx.x;
    const int stride = gridDim.x * R1_THREADS;

    // Grid-stride over float4: coalesced LDG.E.128, compiler unrolls for MLP.
    #pragma unroll 4
    for (int i = idx; i < n4; i += stride) {
        float4 v = __ldg(&x4[i]);
        s += (v.x + v.y) + (v.z + v.w);
    }

    // Warp reduce
    #pragma unroll
    for (int o = 16; o > 0; o >>= 1)
        s += __shfl_down_sync(0xffffffffu, s, o);

    __shared__ float sh[R1_THREADS / 32];
    if ((threadIdx.x & 31) == 0) sh[threadIdx.x >> 5] = s;
    __syncthreads();

    if (threadIdx.x < 32) {
        float v = (threadIdx.x < R1_THREADS / 32) ? sh[threadIdx.x] : 0.0f;
        #pragma unroll
        for (int o = 4; o > 0; o >>= 1)
            v += __shfl_down_sync(0xffffffffu, v, o);
        if (threadIdx.x == 0) g_partials[blockIdx.x] = v;  // overwrite: deterministic
    }
}

__global__ __launch_bounds__(1024) void reduce_pass2(
    const float* __restrict__ a, const float* __restrict__ b,
    float* __restrict__ out)
{
    float s = 0.0f;
    for (int i = threadIdx.x; i < R1_BLOCKS; i += 1024)
        s += g_partials[i];

    #pragma unroll
    for (int o = 16; o > 0; o >>= 1)
        s += __shfl_down_sync(0xffffffffu, s, o);

    __shared__ float sh[32];
    if ((threadIdx.x & 31) == 0) sh[threadIdx.x >> 5] = s;
    __syncthreads();

    if (threadIdx.x < 32) {
        float v = sh[threadIdx.x];
        #pragma unroll
        for (int o = 16; o > 0; o >>= 1)
            v += __shfl_down_sync(0xffffffffu, v, o);
        if (threadIdx.x == 0)
            *out = v * (*a) * (*b);
    }
}

extern "C" void kernel_launch(void* const* d_in, const int* in_sizes, int n_in,
                              void* d_out, int out_size)
{
    const float* x = (const float*)d_in[0];
    const float* a = (const float*)d_in[1];
    const float* b = (const float*)d_in[2];
    float* out = (float*)d_out;

    const int n = in_sizes[0];     // 67108864, divisible by 4
    const int n4 = n >> 2;

    reduce_pass1<<<R1_BLOCKS, R1_THREADS>>>((const float4*)x, n4);
    reduce_pass2<<<1, 1024>>>(a, b, out);
}

// round 4
// speedup vs baseline: 1.0020x; 1.0020x over previous
#include <cuda_runtime.h>

// out = sum(x) * a * b ; x is 8192*8192 fp32, a,b device scalars.
// Single fused kernel: grid-stride float4 reduction -> per-block partial ->
// last-block-done final reduction (deterministic: partials summed in fixed
// order by whichever block finishes last; counter reset for graph replay).

#define NBLOCKS 1184   // 8 CTAs/SM * 148 SMs
#define NTHREADS 256

__device__ float g_partials[NBLOCKS];
__device__ unsigned int g_count;   // zero-initialized; reset by last block

__global__ __launch_bounds__(NTHREADS) void reduce_fused(
    const float4* __restrict__ x4, int n4,
    const float* __restrict__ a, const float* __restrict__ b,
    float* __restrict__ out)
{
    const int tid = threadIdx.x;
    const int stride = NBLOCKS * NTHREADS;
    int i = blockIdx.x * NTHREADS + tid;

    // 4 independent accumulators: breaks the FADD dependency chain so the
    // unrolled loop can keep many LDG.128 in flight.
    float s0 = 0.f, s1 = 0.f, s2 = 0.f, s3 = 0.f;

    // Main unrolled-by-4 grid-stride loop.
    for (; i + 3 * stride < n4; i += 4 * stride) {
        float4 v0 = __ldg(&x4[i]);
        float4 v1 = __ldg(&x4[i + stride]);
        float4 v2 = __ldg(&x4[i + 2 * stride]);
        float4 v3 = __ldg(&x4[i + 3 * stride]);
        s0 += (v0.x + v0.y) + (v0.z + v0.w);
        s1 += (v1.x + v1.y) + (v1.z + v1.w);
        s2 += (v2.x + v2.y) + (v2.z + v2.w);
        s3 += (v3.x + v3.y) + (v3.z + v3.w);
    }
    // Tail
    for (; i < n4; i += stride) {
        float4 v = __ldg(&x4[i]);
        s0 += (v.x + v.y) + (v.z + v.w);
    }
    float s = (s0 + s1) + (s2 + s3);

    // Warp reduce
    #pragma unroll
    for (int o = 16; o > 0; o >>= 1)
        s += __shfl_down_sync(0xffffffffu, s, o);

    __shared__ float sh[NTHREADS / 32];
    __shared__ bool is_last;
    if ((tid & 31) == 0) sh[tid >> 5] = s;
    __syncthreads();

    if (tid < 32) {
        float v = (tid < NTHREADS / 32) ? sh[tid] : 0.0f;
        #pragma unroll
        for (int o = 4; o > 0; o >>= 1)
            v += __shfl_down_sync(0xffffffffu, v, o);
        if (tid == 0) {
            g_partials[blockIdx.x] = v;
            __threadfence();
            unsigned int ticket = atomicAdd(&g_count, 1u);
            is_last = (ticket == NBLOCKS - 1);
        }
    }
    __syncthreads();

    if (!is_last) return;

    // Last block: reduce all partials (fixed order -> deterministic value).
    __threadfence();
    float t = 0.0f;
    for (int j = tid; j < NBLOCKS; j += NTHREADS) {
        float p;
        asm volatile("ld.global.cg.f32 %0, [%1];" : "=f"(p) : "l"(&g_partials[j]));
        t += p;
    }
    #pragma unroll
    for (int o = 16; o > 0; o >>= 1)
        t += __shfl_down_sync(0xffffffffu, t, o);

    if ((tid & 31) == 0) sh[tid >> 5] = t;
    __syncthreads();

    if (tid == 0) {
        float r = 0.0f;
        #pragma unroll
        for (int w = 0; w < NTHREADS / 32; w++) r += sh[w];
        *out = r * (*a) * (*b);
        g_count = 0;   // reset for next graph replay
    }
}

extern "C" void kernel_launch(void* const* d_in, const int* in_sizes, int n_in,
                              void* d_out, int out_size)
{
    const float* x = (const float*)d_in[0];
    const float* a = (const float*)d_in[1];
    const float* b = (const float*)d_in[2];
    float* out = (float*)d_out;

    const int n4 = in_sizes[0] >> 2;   // 64Mi / 4

    reduce_fused<<<NBLOCKS, NTHREADS>>>((const float4*)x, n4, a, b, out);
}

// round 5
// speedup vs baseline: 1.1316x; 1.1294x over previous
#include <cuda_runtime.h>

// out = sum(x) * a * b ; x is 8192*8192 fp32, a,b device scalars.
// Single fused kernel. Grid sized to EXACTLY one resident wave:
// regs=34..40 => 6 CTAs/SM at 256 threads => 148*6 = 888 blocks.

#define NBLOCKS 888    // 6 CTAs/SM * 148 SMs — one balanced wave at regs~40
#define NTHREADS 256

__device__ float g_partials[NBLOCKS];
__device__ unsigned int g_count;   // zero-init; reset by last block each run

__global__ __launch_bounds__(NTHREADS) void reduce_fused(
    const float4* __restrict__ x4, int n4,
    const float* __restrict__ a, const float* __restrict__ b,
    float* __restrict__ out)
{
    const int tid = threadIdx.x;
    const int stride = NBLOCKS * NTHREADS;
    int i = blockIdx.x * NTHREADS + tid;

    // 4 independent accumulators -> 4 LDG.128 in flight per thread.
    float s0 = 0.f, s1 = 0.f, s2 = 0.f, s3 = 0.f;

    for (; i + 3 * stride < n4; i += 4 * stride) {
        float4 v0 = __ldg(&x4[i]);
        float4 v1 = __ldg(&x4[i + stride]);
        float4 v2 = __ldg(&x4[i + 2 * stride]);
        float4 v3 = __ldg(&x4[i + 3 * stride]);
        s0 += (v0.x + v0.y) + (v0.z + v0.w);
        s1 += (v1.x + v1.y) + (v1.z + v1.w);
        s2 += (v2.x + v2.y) + (v2.z + v2.w);
        s3 += (v3.x + v3.y) + (v3.z + v3.w);
    }
    for (; i < n4; i += stride) {
        float4 v = __ldg(&x4[i]);
        s0 += (v.x + v.y) + (v.z + v.w);
    }
    float s = (s0 + s1) + (s2 + s3);

    #pragma unroll
    for (int o = 16; o > 0; o >>= 1)
        s += __shfl_down_sync(0xffffffffu, s, o);

    __shared__ float sh[NTHREADS / 32];
    __shared__ bool is_last;
    if ((tid & 31) == 0) sh[tid >> 5] = s;
    __syncthreads();

    if (tid < 32) {
        float v = (tid < NTHREADS / 32) ? sh[tid] : 0.0f;
        #pragma unroll
        for (int o = 4; o > 0; o >>= 1)
            v += __shfl_down_sync(0xffffffffu, v, o);
        if (tid == 0) {
            g_partials[blockIdx.x] = v;
            __threadfence();
            unsigned int ticket = atomicAdd(&g_count, 1u);
            is_last = (ticket == NBLOCKS - 1);
        }
    }
    __syncthreads();

    if (!is_last) return;

    // Last block: reduce all partials (fixed order -> deterministic value).
    __threadfence();
    float t = 0.0f;
    for (int j = tid; j < NBLOCKS; j += NTHREADS) {
        float p;
        asm volatile("ld.global.cg.f32 %0, [%1];" : "=f"(p) : "l"(&g_partials[j]));
        t += p;
    }
    #pragma unroll
    for (int o = 16; o > 0; o >>= 1)
        t += __shfl_down_sync(0xffffffffu, t, o);

    if ((tid & 31) == 0) sh[tid >> 5] = t;
    __syncthreads();

    if (tid == 0) {
        float r = 0.0f;
        #pragma unroll
        for (int w = 0; w < NTHREADS / 32; w++) r += sh[w];
        *out = r * (*a) * (*b);
        g_count = 0;   // reset for next graph replay
    }
}

extern "C" void kernel_launch(void* const* d_in, const int* in_sizes, int n_in,
                              void* d_out, int out_size)
{
    const float* x = (const float*)d_in[0];
    const float* a = (const float*)d_in[1];
    const float* b = (const float*)d_in[2];
    float* out = (float*)d_out;

    const int n4 = in_sizes[0] >> 2;   // 16Mi float4

    reduce_fused<<<NBLOCKS, NTHREADS>>>((const float4*)x, n4, a, b, out);
}